// round 15
// baseline (speedup 1.0000x reference)
#include <cuda_runtime.h>
#include <cstdint>

// Graph_Learn: persistent work-stealing fused kernel, packed f32x2.
// S[b,t,i,j] = exp(relu(sum_f a_f*|xi-xj|)) / rowsum
// (row sum == reference column sum by exact bitwise symmetry of tmpS).
// 456 persistent blocks pull (bt, 8-row-tile) items from a global counter.
// Token = atomicAdd % M with M = ITEMS + nblocks: each launch consumes exactly
// M increments (each block ends on one failing token), so graph replays are
// deterministic with no counter reset.

#define Vn 256
#define Fn 64
#define Rr 8            // rows per item
#define PAD 68          // floats per smem row (17 * 16B, odd quad stride)

#define SMEM_AS   (Vn * PAD)          // a[64]
#define SMEM_FLOATS (SMEM_AS + Fn)
#define SMEM_BYTES  (SMEM_FLOATS * 4)

typedef unsigned long long u64;

__device__ unsigned int g_ctr;        // monotone token counter (never reset)

__device__ __forceinline__ u64 f2add(u64 a, u64 b) {
    u64 d; asm("add.rn.f32x2 %0,%1,%2;" : "=l"(d) : "l"(a), "l"(b)); return d;
}
__device__ __forceinline__ u64 f2fma(u64 a, u64 b, u64 c) {
    u64 d; asm("fma.rn.f32x2 %0,%1,%2,%3;" : "=l"(d) : "l"(a), "l"(b), "l"(c)); return d;
}
__device__ __forceinline__ u64 f2abs(u64 a) {
    u64 d; asm("and.b64 %0,%1,0x7FFFFFFF7FFFFFFF;" : "=l"(d) : "l"(a)); return d;
}
__device__ __forceinline__ u64 packf2(float lo, float hi) {
    u64 d; asm("mov.b64 %0,{%1,%2};" : "=l"(d) : "f"(lo), "f"(hi)); return d;
}
__device__ __forceinline__ void unpackf2(u64 v, float& lo, float& hi) {
    asm("mov.b64 {%0,%1},%2;" : "=f"(lo), "=f"(hi) : "l"(v));
}
__device__ __forceinline__ void lds_2x64(uint32_t addr, u64& p0, u64& p1) {
    asm volatile("ld.shared.v2.u64 {%0,%1},[%2];" : "=l"(p0), "=l"(p1) : "r"(addr));
}

__global__ __launch_bounds__(256, 3)
void gl_kernel(const float* __restrict__ x, const float* __restrict__ a,
               float* __restrict__ out, unsigned int ITEMS, unsigned int M)
{
    extern __shared__ float sm[];
    float* xs  = sm;             // [Vn][PAD]
    float* as_ = sm + SMEM_AS;   // a[64]
    __shared__ float wsum[Rr * 8];
    __shared__ float rdn[Rr];
    __shared__ unsigned int s_tok;

    const int tid  = threadIdx.x;
    const int j    = tid;
    const int lane = tid & 31, w = tid >> 5;

    const uint32_t xs_sh = (uint32_t)__cvta_generic_to_shared(xs);
    const uint32_t as_sh = (uint32_t)__cvta_generic_to_shared(as_);

    int cur_bt = -1;

    for (;;) {
        if (tid == 0) s_tok = atomicAdd(&g_ctr, 1u) % M;
        __syncthreads();                 // publishes token; also fences smem reuse
        const unsigned int t = s_tok;
        if (t >= ITEMS) break;           // block-uniform exit (one fail per block)

        const int bt   = (int)(t >> 5);  // 32 tiles per bt (bt-major order)
        const int tile = (int)(t & 31);
        const int i0   = tile * Rr;

        if (bt != cur_bt) {
            // ---- (re)stage x[bt] slice into padded smem ----
            const float4* xp = (const float4*)(x + (size_t)bt * Vn * Fn);
            #pragma unroll
            for (int it = 0; it < 16; ++it) {
                int k = tid + it * 256;
                float4 v = xp[k];
                int row = k >> 4;
                int fc  = (k & 15) << 2;
                *(float4*)&xs[row * PAD + fc] = v;
            }
            if (cur_bt < 0 && tid < Fn) as_[tid] = a[tid];
            cur_bt = bt;
            __syncthreads();
        }

        u64 acc[Rr];
        #pragma unroll
        for (int r = 0; r < Rr; ++r) acc[r] = 0ull;

        // ---- main: 8 f-chunks of 8 floats (4 packed pairs per chunk) ----
        #pragma unroll 1
        for (int c = 0; c < 8; ++c) {
            const int f0 = c << 3;
            u64 nxj[4], av[4];
            {
                const uint32_t jb = xs_sh + (uint32_t)((j * PAD + f0) * 4);
                u64 tt[4];
                lds_2x64(jb + 0,  tt[0], tt[1]);
                lds_2x64(jb + 16, tt[2], tt[3]);
                #pragma unroll
                for (int q = 0; q < 4; ++q) {
                    float lo, hi; unpackf2(tt[q], lo, hi);
                    nxj[q] = packf2(-lo, -hi);
                }
                const uint32_t ab = as_sh + (uint32_t)(f0 * 4);
                lds_2x64(ab + 0,  av[0], av[1]);
                lds_2x64(ab + 16, av[2], av[3]);
            }
            #pragma unroll
            for (int r = 0; r < Rr; ++r) {
                const uint32_t base = xs_sh + (uint32_t)(((i0 + r) * PAD + f0) * 4);
                u64 xi[4];
                lds_2x64(base + 0,  xi[0], xi[1]);   // warp-uniform broadcast
                lds_2x64(base + 16, xi[2], xi[3]);
                u64 s = acc[r];
                #pragma unroll
                for (int k = 0; k < 4; ++k) {
                    u64 d = f2abs(f2add(xi[k], nxj[k]));   // ADD2 + 2xLOP3
                    s = f2fma(d, av[k], s);                // FFMA2
                }
                acc[r] = s;
            }
        }

        // ---- tmpS = exp(relu(lo+hi)) ----
        float f[Rr];
        #pragma unroll
        for (int r = 0; r < Rr; ++r) {
            float lo, hi;
            unpackf2(acc[r], lo, hi);
            f[r] = __expf(fmaxf(lo + hi, 0.f));
        }

        // ---- denom: row sums (== column sums by exact symmetry) ----
        #pragma unroll
        for (int r = 0; r < Rr; ++r) {
            float v = f[r];
            v += __shfl_xor_sync(0xffffffffu, v, 16);
            v += __shfl_xor_sync(0xffffffffu, v, 8);
            v += __shfl_xor_sync(0xffffffffu, v, 4);
            v += __shfl_xor_sync(0xffffffffu, v, 2);
            v += __shfl_xor_sync(0xffffffffu, v, 1);
            if (lane == 0) wsum[r * 8 + w] = v;
        }
        __syncthreads();
        if (tid < Rr) {
            float d = 0.f;
            #pragma unroll
            for (int q = 0; q < 8; ++q) d += wsum[tid * 8 + q];
            rdn[tid] = __fdividef(1.0f, d);
        }
        __syncthreads();

        // ---- normalize + coalesced store ----
        float* op = out + ((size_t)bt * Vn + i0) * Vn + j;
        #pragma unroll
        for (int r = 0; r < Rr; ++r)
            op[(size_t)r * Vn] = f[r] * rdn[r];
    }
}

extern "C" void kernel_launch(void* const* d_in, const int* in_sizes, int n_in,
                              void* d_out, int out_size)
{
    const float* x = (const float*)d_in[0];
    const float* a = (const float*)d_in[1];
    if (n_in >= 2 && in_sizes[0] == Fn && in_sizes[1] > Fn) {
        x = (const float*)d_in[1];
        a = (const float*)d_in[0];
    }
    int bt = in_sizes[0] == Fn ? in_sizes[1] / (Vn * Fn) : in_sizes[0] / (Vn * Fn);

    const unsigned int ITEMS = (unsigned int)bt * 32u;   // 8-row tiles
    unsigned int nblocks = 456u;                         // 152 SMs * 3
    if (nblocks > ITEMS) nblocks = ITEMS;
    const unsigned int M = ITEMS + nblocks;

    cudaFuncSetAttribute(gl_kernel, cudaFuncAttributeMaxDynamicSharedMemorySize,
                         SMEM_BYTES);
    gl_kernel<<<nblocks, 256, SMEM_BYTES>>>(x, a, (float*)d_out, ITEMS, M);
}